// round 7
// baseline (speedup 1.0000x reference)
#include <cuda_runtime.h>
#include <cstdint>

#define PI_F 3.14159265358979f

__device__ __forceinline__ uint32_t f2tf32(float f) {
    uint32_t r;
    asm("cvt.rna.tf32.f32 %0, %1;" : "=r"(r) : "f"(f));
    return r;
}

__device__ __forceinline__ void mma8(float* d, const uint32_t* a, const uint32_t* b) {
    asm volatile(
        "mma.sync.aligned.m16n8k8.row.col.f32.tf32.tf32.f32 "
        "{%0,%1,%2,%3}, {%4,%5,%6,%7}, {%8,%9}, {%0,%1,%2,%3};"
        : "+f"(d[0]), "+f"(d[1]), "+f"(d[2]), "+f"(d[3])
        : "r"(a[0]), "r"(a[1]), "r"(a[2]), "r"(a[3]), "r"(b[0]), "r"(b[1]));
}

// ---------------- quantum gate helpers (warp-collective, 2 amps/lane) ----------------
__device__ __forceinline__ void gate_b5(const float2* G,
                                        float& a0r, float& a0i, float& a1r, float& a1i) {
    float2 g00 = G[0], g01 = G[1], g10 = G[2], g11 = G[3];
    float n0r = g00.x * a0r - g00.y * a0i + g01.x * a1r - g01.y * a1i;
    float n0i = g00.x * a0i + g00.y * a0r + g01.x * a1i + g01.y * a1r;
    float n1r = g10.x * a0r - g10.y * a0i + g11.x * a1r - g11.y * a1i;
    float n1i = g10.x * a0i + g10.y * a0r + g11.x * a1i + g11.y * a1r;
    a0r = n0r; a0i = n0i; a1r = n1r; a1i = n1i;
}

__device__ __forceinline__ void gate_lo(int bbit, int lane, const float2* G,
                                        float& a0r, float& a0i, float& a1r, float& a1i) {
    const unsigned F = 0xffffffffu;
    float2 g00 = G[0], g01 = G[1], g10 = G[2], g11 = G[3];
    int m = 1 << bbit;
    float p0r = __shfl_xor_sync(F, a0r, m);
    float p0i = __shfl_xor_sync(F, a0i, m);
    float p1r = __shfl_xor_sync(F, a1r, m);
    float p1i = __shfl_xor_sync(F, a1i, m);
    bool hi = (lane >> bbit) & 1;
    float Ar = hi ? g11.x : g00.x, Ai = hi ? g11.y : g00.y;
    float Pr = hi ? g10.x : g01.x, Pi = hi ? g10.y : g01.y;
    float n0r = Ar * a0r - Ai * a0i + Pr * p0r - Pi * p0i;
    float n0i = Ar * a0i + Ai * a0r + Pr * p0i + Pi * p0r;
    float n1r = Ar * a1r - Ai * a1i + Pr * p1r - Pi * p1i;
    float n1i = Ar * a1i + Ai * a1r + Pr * p1i + Pi * p1r;
    a0r = n0r; a0i = n0i; a1r = n1r; a1i = n1i;
}

__device__ __forceinline__ int ring_src(int s) {
    int b5 = (s >> 5) & 1, b4 = (s >> 4) & 1, b3 = (s >> 3) & 1;
    int b2 = (s >> 2) & 1, b1 = (s >> 1) & 1, b0 = s & 1;
    b5 ^= b0; b0 ^= b1; b1 ^= b2; b2 ^= b3; b3 ^= b4; b4 ^= b5;
    return (b5 << 5) | (b4 << 4) | (b3 << 3) | (b2 << 2) | (b1 << 1) | b0;
}

__device__ __forceinline__ void ring2(int q0l, int q0h, int q1l, int q1h,
                                      float& a0r, float& a0i, float& a1r, float& a1i) {
    const unsigned F = 0xffffffffu;
    float x0r = __shfl_sync(F, a0r, q0l);
    float y0r = __shfl_sync(F, a1r, q0l);
    float x0i = __shfl_sync(F, a0i, q0l);
    float y0i = __shfl_sync(F, a1i, q0l);
    float x1r = __shfl_sync(F, a0r, q1l);
    float y1r = __shfl_sync(F, a1r, q1l);
    float x1i = __shfl_sync(F, a0i, q1l);
    float y1i = __shfl_sync(F, a1i, q1l);
    a0r = q0h ? y0r : x0r; a0i = q0h ? y0i : x0i;
    a1r = q1h ? y1r : x1r; a1i = q1h ? y1i : x1i;
}

// ---------------- fused kernel ----------------
// 256 CTAs x 256 thr (8 warps). CTA = 128 px (2 image rows) x 72 outputs.
// K=576 in 8 chunks of 72 (9 k-tiles of 8). A-fragments live in registers.
// dyn smem: mainloop [xs 8448 | smB 20736]; tail reuses it all as stg[128][69].
#define XS_OFF  0
#define SMB_OFF 8448
#define FUSED_SMEM 35328

__global__ __launch_bounds__(256, 3) void k_fused(
    const float* __restrict__ x, const float* __restrict__ wr,
    const float* __restrict__ wd, const float* __restrict__ rb,
    const float* __restrict__ db, const float* __restrict__ style,
    const float* __restrict__ sw, const float* __restrict__ sb,
    const float* __restrict__ qcnn, const float* __restrict__ meas,
    const float* __restrict__ ow, const float* __restrict__ ob,
    float* __restrict__ out) {
    extern __shared__ char smem[];
    float (*xs)[4][66] = (float (*)[4][66])(smem + XS_OFF);
    char* smB = smem + SMB_OFF;                        // B frags [kt][nt][lane] uint2
    __shared__ float s_phiadd[6];
    __shared__ float s_cb0[6], s_sb0[6];
    __shared__ float2 s_g1[6][4], s_g2[6][4];
    __shared__ float sphi_all[8][96];                  // [warp][16 px][6 wires]

    const unsigned F = 0xffffffffu;
    int tid = threadIdx.x;
    int lane = tid & 31;
    int wid = tid >> 5;               // warp = m-tile
    int g = lane >> 2, t4 = lane & 3;
    int px0 = blockIdx.x << 7;
    int b = px0 >> 12;
    int hwbase = px0 & 4095;
    int h0 = hwbase >> 6;             // 128 px = 2 full image rows h0, h0+1

    // --- small tables ---
    if (tid < 6) {
        int i = tid;
        float b0 = qcnn[i * 6 + 3];
        s_cb0[i] = cosf(0.5f * b0);
        s_sb0[i] = sinf(0.5f * b0);
        float a1 = qcnn[36 + i * 6];
        float b1 = qcnn[36 + i * 6 + 3];
        float ca = cosf(0.5f * a1), sa = sinf(0.5f * a1);
        float cb = cosf(0.5f * b1), sbv = sinf(0.5f * b1);
        s_g1[i][0] = make_float2(cb * ca, -sbv * ca);
        s_g1[i][1] = make_float2(-cb * sa, sbv * sa);
        s_g1[i][2] = make_float2(cb * sa, sbv * sa);
        s_g1[i][3] = make_float2(cb * ca, sbv * ca);
        float th = meas[i * 3 + 0], phv = meas[i * 3 + 1], la = meas[i * 3 + 2];
        float ct = cosf(0.5f * th), st = sinf(0.5f * th);
        s_g2[i][0] = make_float2(ct, 0.f);
        s_g2[i][1] = make_float2(-cosf(la) * st, -sinf(la) * st);
        s_g2[i][2] = make_float2(cosf(phv) * st, sinf(phv) * st);
        s_g2[i][3] = make_float2(cosf(phv + la) * ct, sinf(phv + la) * ct);
    }
    if (wid < 6) {   // style projection for this batch image, wire = wid
        float4 a = reinterpret_cast<const float4*>(style + b * 128)[lane];
        float4 w = reinterpret_cast<const float4*>(sw + wid * 128)[lane];
        float acc0 = a.x * w.x + a.y * w.y + a.z * w.z + a.w * w.w;
#pragma unroll
        for (int o = 16; o; o >>= 1) acc0 += __shfl_xor_sync(F, acc0, o);
        if (lane == 0)
            s_phiadd[wid] = PI_F * tanhf(acc0 + sb[wid]) + qcnn[wid * 6];
    }

    float acc[9][4];
#pragma unroll
    for (int j = 0; j < 9; j++)
#pragma unroll
        for (int c = 0; c < 4; c++) acc[j][c] = 0.f;

    // --- mainloop over K chunks ---
    for (int chunk = 0; chunk < 8; chunk++) {
        __syncthreads();
        // stage x tile: 8 ci x 4 rows x 66 cols, zero-padded halo (coalesced)
        for (int i = tid; i < 2112; i += 256) {
            int ci = i / 264; int rem = i - ci * 264;
            int r = rem / 66; int cpos = rem - r * 66;
            int gh = h0 - 1 + r, gw = cpos - 1;
            float v = 0.f;
            if ((unsigned)gh < 64u && (unsigned)gw < 64u)
                v = __ldg(x + (((b << 6) + (chunk << 3) + ci) << 12) + (gh << 6) + gw);
            xs[ci][r][cpos] = v;
        }
        // stage weights straight into B-fragment layout (coalesced LDG.128)
        // element (n, k): kt=k/8, half=(k%8)/4, ln=(n%8)*4+(k%4)
        // smB float index: ((kt*9 + n/8)*32 + ln)*2 + half
        for (int i = tid; i < 1260; i += 256) {
            int n = i / 18, qf = i - n * 18;
            const float* src = (n < 64) ? (wr + n * 576) : (wd + (n - 64) * 576);
            float4 v = *reinterpret_cast<const float4*>(src + chunk * 72 + (qf << 2));
            int kt = qf >> 1, half = qf & 1;
            uint32_t* dst = reinterpret_cast<uint32_t*>(smB) +
                            (((kt * 9 + (n >> 3)) * 32 + ((n & 7) << 2)) << 1) + half;
            dst[0] = f2tf32(v.x);
            dst[2] = f2tf32(v.y);
            dst[4] = f2tf32(v.z);
            dst[6] = f2tf32(v.w);
        }
        __syncthreads();
        // per k-tile: build A fragment in registers, run 9 mma
#pragma unroll 3
        for (int kt = 0; kt < 9; kt++) {
            uint32_t A[4];
#pragma unroll
            for (int half = 0; half < 2; half++) {
                int kloc = kt * 8 + t4 + 4 * half;
                int ci = kloc / 9;
                int kk = kloc - ci * 9;
                int kh = kk / 3, kw = kk - kh * 3;
#pragma unroll
                for (int rr = 0; rr < 2; rr++) {
                    int px = wid * 16 + g + 8 * rr;
                    int r = (px >> 6) + kh;
                    int cpos = (px & 63) + kw;
                    A[half * 2 + rr] = f2tf32(xs[ci][r][cpos]);
                }
            }
#pragma unroll
            for (int nt = 0; nt < 9; nt++) {
                uint2 bb = *reinterpret_cast<const uint2*>(
                    smB + ((kt * 9 + nt) * 32 + lane) * 8);
                uint32_t B[2] = {bb.x, bb.y};
                mma8(acc[nt], A, B);
            }
        }
    }
    __syncthreads();   // all mma done; whole dyn smem free for tail scratch

    // --- phi staging: nt=8 holds channels 64..71 (angle wires 0..5 at t4<3) ---
    float* sphi = sphi_all[wid];                 // [16 px][6 wires]
    if (t4 < 3) {
#pragma unroll
        for (int c = 0; c < 4; c++) {
            int pxl = g + 8 * (c >> 1);
            int wire = 2 * t4 + (c & 1);
            sphi[pxl * 6 + wire] =
                PI_F * tanhf(acc[8][c] + __ldg(db + wire)) + s_phiadd[wire];
        }
    }
    __syncwarp();

    // --- circuit per pixel (warp-collective), stage outputs in stg[px][69] ---
    float* stg = (float*)smem;                   // [128 px][69] floats
    int q0 = ring_src(lane), q1 = ring_src(lane + 32);
    int q0l = q0 & 31, q0h = q0 >> 5;
    int q1l = q1 & 31, q1h = q1 >> 5;
    float obr0 = __ldg(ob + lane), obr1 = __ldg(ob + lane + 32);
    float owA[6], owB[6];
#pragma unroll
    for (int i = 0; i < 6; i++) {
        owA[i] = __ldg(ow + lane * 6 + i);
        owB[i] = __ldg(ow + (lane + 32) * 6 + i);
    }

    for (int pxl = 0; pxl < 16; pxl++) {
        float myphi = (lane < 6) ? sphi[pxl * 6 + lane] : 0.f;
        float sv_s, cv_s;
        __sincosf(0.5f * myphi, &sv_s, &cv_s);   // real work on lanes 0-5 only

        float u0r[6], u0i[6], u1r[6], u1i[6];
#pragma unroll
        for (int i = 0; i < 6; i++) {
            float cv = __shfl_sync(F, cv_s, i);
            float sv = __shfl_sync(F, sv_s, i);
            float cb = s_cb0[i], sbv = s_sb0[i];
            u0r[i] = cv * cb; u0i[i] = -cv * sbv;
            u1r[i] = sv * cb; u1i[i] = sv * sbv;
        }
        float a0r = 1.f, a0i = 0.f, a1r, a1i;
#pragma unroll
        for (int i = 0; i < 6; i++) {
            int bit = (lane >> (5 - i)) & 1;
            float ur = bit ? u1r[i] : u0r[i];
            float ui = bit ? u1i[i] : u0i[i];
            float nr = a0r * ur - a0i * ui;
            float ni = a0r * ui + a0i * ur;
            a0r = nr; a0i = ni;
        }
        a1r = u1r[0]; a1i = u1i[0];
#pragma unroll
        for (int i = 1; i < 6; i++) {
            int bit = (lane >> (5 - i)) & 1;
            float ur = bit ? u1r[i] : u0r[i];
            float ui = bit ? u1i[i] : u0i[i];
            float nr = a1r * ur - a1i * ui;
            float ni = a1r * ui + a1i * ur;
            a1r = nr; a1i = ni;
        }

        ring2(q0l, q0h, q1l, q1h, a0r, a0i, a1r, a1i);
#pragma unroll
        for (int i = 0; i < 6; i++) {
            if (i == 0) gate_b5(s_g1[0], a0r, a0i, a1r, a1i);
            else        gate_lo(5 - i, lane, s_g1[i], a0r, a0i, a1r, a1i);
        }
        ring2(q0l, q0h, q1l, q1h, a0r, a0i, a1r, a1i);
#pragma unroll
        for (int i = 0; i < 6; i++) {
            if (i == 0) gate_b5(s_g2[0], a0r, a0i, a1r, a1i);
            else        gate_lo(5 - i, lane, s_g2[i], a0r, a0i, a1r, a1i);
        }

        float p0 = a0r * a0r + a0i * a0i;
        float p1 = a1r * a1r + a1i * a1i;
        // Walsh reduction: ev0 = sum(p0-p1); ev_i = F[1<<(5-i)] of (p0+p1)
        float t0 = p0 + p1, dd = p0 - p1;
#pragma unroll
        for (int m = 16; m; m >>= 1) dd += __shfl_xor_sync(F, dd, m);
#pragma unroll
        for (int m = 16; m; m >>= 1) {
            float o = __shfl_xor_sync(F, t0, m);
            t0 = ((lane & m) ? -t0 : t0) + o;
        }
        float e1 = __shfl_sync(F, t0, 16);
        float e2 = __shfl_sync(F, t0, 8);
        float e3 = __shfl_sync(F, t0, 4);
        float e4 = __shfl_sync(F, t0, 2);
        float e5 = __shfl_sync(F, t0, 1);

        float o0 = fmaf(owA[0], dd, obr0);
        float o1 = fmaf(owB[0], dd, obr1);
        o0 = fmaf(owA[1], e1, o0); o1 = fmaf(owB[1], e1, o1);
        o0 = fmaf(owA[2], e2, o0); o1 = fmaf(owB[2], e2, o1);
        o0 = fmaf(owA[3], e3, o0); o1 = fmaf(owB[3], e3, o1);
        o0 = fmaf(owA[4], e4, o0); o1 = fmaf(owB[4], e4, o1);
        o0 = fmaf(owA[5], e5, o0); o1 = fmaf(owB[5], e5, o1);

        int px = wid * 16 + pxl;
        stg[px * 69 + lane] = o0;
        stg[px * 69 + lane + 32] = o1;
    }
    __syncwarp();

    // --- conv epilogue: add conv + bias into stg ---
#pragma unroll
    for (int nt = 0; nt < 8; nt++) {
#pragma unroll
        for (int c = 0; c < 4; c++) {
            int pxl = g + 8 * (c >> 1);
            int co = nt * 8 + 2 * t4 + (c & 1);
            int px = wid * 16 + pxl;
            stg[px * 69 + co] += acc[nt][c] + __ldg(rb + co);
        }
    }
    __syncthreads();

    // --- fully coalesced final write: 64 co rows x 128 contiguous px ---
    for (int i = tid; i < 8192; i += 256) {
        int co = i >> 7, px = i & 127;
        out[(((b << 6) + co) << 12) + hwbase + px] = stg[px * 69 + co];
    }
}

// ---------------- launch ----------------
extern "C" void kernel_launch(void* const* d_in, const int* in_sizes, int n_in,
                              void* d_out, int out_size) {
    const float* x     = (const float*)d_in[0];
    const float* style = (const float*)d_in[1];
    const float* wd    = (const float*)d_in[2];   // data_proj_w [6,576]
    const float* db    = (const float*)d_in[3];   // data_proj_b [6]
    const float* sw    = (const float*)d_in[4];   // style_to_data_w [6,128]
    const float* sb    = (const float*)d_in[5];   // style_to_data_b [6]
    const float* qcnn  = (const float*)d_in[6];   // [2,6,2,3]
    const float* meas  = (const float*)d_in[7];   // [6,3]
    const float* ow    = (const float*)d_in[8];   // out_proj_w [64,6]
    const float* ob    = (const float*)d_in[9];   // out_proj_b [64]
    const float* wr    = (const float*)d_in[10];  // res_proj_w [64,576]
    const float* rb    = (const float*)d_in[11];  // res_proj_b [64]
    float* out = (float*)d_out;

    cudaFuncSetAttribute(k_fused, cudaFuncAttributeMaxDynamicSharedMemorySize, FUSED_SMEM);
    k_fused<<<256, 256, FUSED_SMEM>>>(x, wr, wd, rb, db, style, sw, sb,
                                      qcnn, meas, ow, ob, out);
}

// round 8
// speedup vs baseline: 1.2361x; 1.2361x over previous
#include <cuda_runtime.h>
#include <cstdint>

#define PI_F 3.14159265358979f

__device__ __forceinline__ uint32_t f2tf32(float f) {
    uint32_t r;
    asm("cvt.rna.tf32.f32 %0, %1;" : "=r"(r) : "f"(f));
    return r;
}

__device__ __forceinline__ void mma8(float* d, const uint32_t* a, const uint32_t* b) {
    asm volatile(
        "mma.sync.aligned.m16n8k8.row.col.f32.tf32.tf32.f32 "
        "{%0,%1,%2,%3}, {%4,%5,%6,%7}, {%8,%9}, {%0,%1,%2,%3};"
        : "+f"(d[0]), "+f"(d[1]), "+f"(d[2]), "+f"(d[3])
        : "r"(a[0]), "r"(a[1]), "r"(a[2]), "r"(a[3]), "r"(b[0]), "r"(b[1]));
}

// ---------------- quantum gate helpers, 2-pixel ILP versions ----------------
__device__ __forceinline__ void gate_b5_2(const float2* G,
                                          float* a0r, float* a0i, float* a1r, float* a1i) {
    float2 g00 = G[0], g01 = G[1], g10 = G[2], g11 = G[3];
#pragma unroll
    for (int j = 0; j < 2; j++) {
        float n0r = g00.x * a0r[j] - g00.y * a0i[j] + g01.x * a1r[j] - g01.y * a1i[j];
        float n0i = g00.x * a0i[j] + g00.y * a0r[j] + g01.x * a1i[j] + g01.y * a1r[j];
        float n1r = g10.x * a0r[j] - g10.y * a0i[j] + g11.x * a1r[j] - g11.y * a1i[j];
        float n1i = g10.x * a0i[j] + g10.y * a0r[j] + g11.x * a1i[j] + g11.y * a1r[j];
        a0r[j] = n0r; a0i[j] = n0i; a1r[j] = n1r; a1i[j] = n1i;
    }
}

__device__ __forceinline__ void gate_lo_2(int bbit, int lane, const float2* G,
                                          float* a0r, float* a0i, float* a1r, float* a1i) {
    const unsigned F = 0xffffffffu;
    float2 g00 = G[0], g01 = G[1], g10 = G[2], g11 = G[3];
    int m = 1 << bbit;
    bool hi = (lane >> bbit) & 1;
    float Ar = hi ? g11.x : g00.x, Ai = hi ? g11.y : g00.y;
    float Pr = hi ? g10.x : g01.x, Pi = hi ? g10.y : g01.y;
#pragma unroll
    for (int j = 0; j < 2; j++) {
        float p0r = __shfl_xor_sync(F, a0r[j], m);
        float p0i = __shfl_xor_sync(F, a0i[j], m);
        float p1r = __shfl_xor_sync(F, a1r[j], m);
        float p1i = __shfl_xor_sync(F, a1i[j], m);
        float n0r = Ar * a0r[j] - Ai * a0i[j] + Pr * p0r - Pi * p0i;
        float n0i = Ar * a0i[j] + Ai * a0r[j] + Pr * p0i + Pi * p0r;
        float n1r = Ar * a1r[j] - Ai * a1i[j] + Pr * p1r - Pi * p1i;
        float n1i = Ar * a1i[j] + Ai * a1r[j] + Pr * p1i + Pi * p1r;
        a0r[j] = n0r; a0i[j] = n0i; a1r[j] = n1r; a1i[j] = n1i;
    }
}

__device__ __forceinline__ int ring_src(int s) {
    int b5 = (s >> 5) & 1, b4 = (s >> 4) & 1, b3 = (s >> 3) & 1;
    int b2 = (s >> 2) & 1, b1 = (s >> 1) & 1, b0 = s & 1;
    b5 ^= b0; b0 ^= b1; b1 ^= b2; b2 ^= b3; b3 ^= b4; b4 ^= b5;
    return (b5 << 5) | (b4 << 4) | (b3 << 3) | (b2 << 2) | (b1 << 1) | b0;
}

__device__ __forceinline__ void ring2_2(int q0l, int q0h, int q1l, int q1h,
                                        float* a0r, float* a0i, float* a1r, float* a1i) {
    const unsigned F = 0xffffffffu;
#pragma unroll
    for (int j = 0; j < 2; j++) {
        float x0r = __shfl_sync(F, a0r[j], q0l);
        float y0r = __shfl_sync(F, a1r[j], q0l);
        float x0i = __shfl_sync(F, a0i[j], q0l);
        float y0i = __shfl_sync(F, a1i[j], q0l);
        float x1r = __shfl_sync(F, a0r[j], q1l);
        float y1r = __shfl_sync(F, a1r[j], q1l);
        float x1i = __shfl_sync(F, a0i[j], q1l);
        float y1i = __shfl_sync(F, a1i[j], q1l);
        a0r[j] = q0h ? y0r : x0r; a0i[j] = q0h ? y0i : x0i;
        a1r[j] = q1h ? y1r : x1r; a1i[j] = q1h ? y1i : x1i;
    }
}

// ---------------- fused kernel ----------------
// 256 CTAs x 256 thr (8 warps). CTA = 128 px (2 image rows) x 72 outputs.
// K=576 in 8 chunks of 72 (9 k-tiles of 8). Software-pipelined staging.
// dyn smem: mainloop [xs 8448 | smB 20736]; tail reuses all as stg[128][69].
#define SMB_OFF 8448
#define FUSED_SMEM 35328

__global__ __launch_bounds__(256, 2) void k_fused(
    const float* __restrict__ x, const float* __restrict__ wr,
    const float* __restrict__ wd, const float* __restrict__ rb,
    const float* __restrict__ db, const float* __restrict__ style,
    const float* __restrict__ sw, const float* __restrict__ sb,
    const float* __restrict__ qcnn, const float* __restrict__ meas,
    const float* __restrict__ ow, const float* __restrict__ ob,
    float* __restrict__ out) {
    extern __shared__ char smem[];
    uint32_t* xs_u = (uint32_t*)smem;                  // x tile, tf32 bits, linear 2112
    char* smB = smem + SMB_OFF;                        // B frags [kt][nt][lane] uint2
    __shared__ float s_phiadd[6];
    __shared__ float s_cb0[6], s_sb0[6];
    __shared__ float2 s_g1[6][4], s_g2[6][4];
    __shared__ float sphi_all[8][96];                  // [warp][16 px][6 wires]

    const unsigned F = 0xffffffffu;
    int tid = threadIdx.x;
    int lane = tid & 31;
    int wid = tid >> 5;               // warp = m-tile
    int g = lane >> 2, t4 = lane & 3;
    int px0 = blockIdx.x << 7;
    int b = px0 >> 12;
    int hwbase = px0 & 4095;
    int h0 = hwbase >> 6;             // 128 px = 2 full image rows h0, h0+1

    // --- small tables ---
    if (tid < 6) {
        int i = tid;
        float b0 = qcnn[i * 6 + 3];
        s_cb0[i] = cosf(0.5f * b0);
        s_sb0[i] = sinf(0.5f * b0);
        float a1 = qcnn[36 + i * 6];
        float b1 = qcnn[36 + i * 6 + 3];
        float ca = cosf(0.5f * a1), sa = sinf(0.5f * a1);
        float cb = cosf(0.5f * b1), sbv = sinf(0.5f * b1);
        s_g1[i][0] = make_float2(cb * ca, -sbv * ca);
        s_g1[i][1] = make_float2(-cb * sa, sbv * sa);
        s_g1[i][2] = make_float2(cb * sa, sbv * sa);
        s_g1[i][3] = make_float2(cb * ca, sbv * ca);
        float th = meas[i * 3 + 0], phv = meas[i * 3 + 1], la = meas[i * 3 + 2];
        float ct = cosf(0.5f * th), st = sinf(0.5f * th);
        s_g2[i][0] = make_float2(ct, 0.f);
        s_g2[i][1] = make_float2(-cosf(la) * st, -sinf(la) * st);
        s_g2[i][2] = make_float2(cosf(phv) * st, sinf(phv) * st);
        s_g2[i][3] = make_float2(cosf(phv + la) * ct, sinf(phv + la) * ct);
    }
    if (wid < 6) {   // style projection for this batch image, wire = wid
        float4 a = reinterpret_cast<const float4*>(style + b * 128)[lane];
        float4 w = reinterpret_cast<const float4*>(sw + wid * 128)[lane];
        float acc0 = a.x * w.x + a.y * w.y + a.z * w.z + a.w * w.w;
#pragma unroll
        for (int o = 16; o; o >>= 1) acc0 += __shfl_xor_sync(F, acc0, o);
        if (lane == 0)
            s_phiadd[wid] = PI_F * tanhf(acc0 + sb[wid]) + qcnn[wid * 6];
    }

    // --- A-offset table (chunk-invariant): offs[2*kt+half] ---
    int offs[18];
#pragma unroll
    for (int kk2 = 0; kk2 < 18; kk2++) {
        int kt = kk2 >> 1, half = kk2 & 1;
        int kloc = kt * 8 + 4 * half + t4;
        int ci = kloc / 9, kr = kloc - ci * 9;
        offs[kk2] = ci * 264 + (kr / 3) * 66 + (kr - (kr / 3) * 3);
    }
    int base0 = (wid >> 2) * 66 + (wid & 3) * 16 + g;

    float acc[9][4];
#pragma unroll
    for (int j = 0; j < 9; j++)
#pragma unroll
        for (int c = 0; c < 4; c++) acc[j][c] = 0.f;

    float px_x[9];
    float4 px_w[5];

    // --- prefetch chunk 0 ---
#pragma unroll
    for (int it = 0; it < 9; it++) {
        int j = tid + (it << 8);
        float v = 0.f;
        if (it < 8 || tid < 64) {
            int ci = j / 264, rem = j - ci * 264;
            int r = rem / 66, cpos = rem - r * 66;
            int gh = h0 - 1 + r, gw = cpos - 1;
            if ((unsigned)gh < 64u && (unsigned)gw < 64u)
                v = __ldg(x + (((b << 6) + ci) << 12) + (gh << 6) + gw);
        }
        px_x[it] = v;
    }
#pragma unroll
    for (int it = 0; it < 5; it++) {
        if (it < 4 || tid < 236) {
            int j = tid + (it << 8);
            int n = j / 18, qf = j - n * 18;
            const float* src = (n < 64) ? (wr + n * 576) : (wd + (n - 64) * 576);
            px_w[it] = *reinterpret_cast<const float4*>(src + (qf << 2));
        }
    }

    // --- pipelined mainloop ---
    for (int chunk = 0; chunk < 8; chunk++) {
        if (chunk) __syncthreads();           // prev mma done reading smem
        // STS staged regs (cvt at store)
#pragma unroll
        for (int it = 0; it < 9; it++) {
            if (it < 8 || tid < 64)
                xs_u[tid + (it << 8)] = f2tf32(px_x[it]);
        }
#pragma unroll
        for (int it = 0; it < 5; it++) {
            if (it < 4 || tid < 236) {
                int j = tid + (it << 8);
                int n = j / 18, qf = j - n * 18;
                int kt = qf >> 1, half = qf & 1;
                uint32_t* dst = reinterpret_cast<uint32_t*>(smB) +
                                (((kt * 9 + (n >> 3)) * 32 + ((n & 7) << 2)) << 1) + half;
                dst[0] = f2tf32(px_w[it].x);
                dst[2] = f2tf32(px_w[it].y);
                dst[4] = f2tf32(px_w[it].z);
                dst[6] = f2tf32(px_w[it].w);
            }
        }
        __syncthreads();
        // prefetch next chunk (LDG overlaps mma below)
        if (chunk < 7) {
            int cn = chunk + 1;
#pragma unroll
            for (int it = 0; it < 9; it++) {
                int j = tid + (it << 8);
                float v = 0.f;
                if (it < 8 || tid < 64) {
                    int ci = j / 264, rem = j - ci * 264;
                    int r = rem / 66, cpos = rem - r * 66;
                    int gh = h0 - 1 + r, gw = cpos - 1;
                    if ((unsigned)gh < 64u && (unsigned)gw < 64u)
                        v = __ldg(x + (((b << 6) + (cn << 3) + ci) << 12) + (gh << 6) + gw);
                }
                px_x[it] = v;
            }
#pragma unroll
            for (int it = 0; it < 5; it++) {
                if (it < 4 || tid < 236) {
                    int j = tid + (it << 8);
                    int n = j / 18, qf = j - n * 18;
                    const float* src = (n < 64) ? (wr + n * 576) : (wd + (n - 64) * 576);
                    px_w[it] = *reinterpret_cast<const float4*>(src + cn * 72 + (qf << 2));
                }
            }
        }
        // mma phase (fully unrolled, const offsets)
#pragma unroll
        for (int kt = 0; kt < 9; kt++) {
            uint32_t A[4];
            A[0] = xs_u[offs[2 * kt] + base0];
            A[1] = xs_u[offs[2 * kt] + base0 + 8];
            A[2] = xs_u[offs[2 * kt + 1] + base0];
            A[3] = xs_u[offs[2 * kt + 1] + base0 + 8];
#pragma unroll
            for (int nt = 0; nt < 9; nt++) {
                uint2 bb = *reinterpret_cast<const uint2*>(
                    smB + ((kt * 9 + nt) * 32 + lane) * 8);
                uint32_t B[2] = {bb.x, bb.y};
                mma8(acc[nt], A, B);
            }
        }
    }
    __syncthreads();   // mma done; dyn smem free for tail scratch

    float* stg = (float*)smem;                   // [128 px][69] floats
    float* sphi = sphi_all[wid];                 // [16 px][6 wires]

    // --- phase 1: phi staging + conv epilogue (frees acc) ---
    if (t4 < 3) {
#pragma unroll
        for (int c = 0; c < 4; c++) {
            int pxl = g + 8 * (c >> 1);
            int wire = 2 * t4 + (c & 1);
            sphi[pxl * 6 + wire] =
                PI_F * tanhf(acc[8][c] + __ldg(db + wire)) + s_phiadd[wire];
        }
    }
#pragma unroll
    for (int nt = 0; nt < 8; nt++) {
#pragma unroll
        for (int c = 0; c < 4; c++) {
            int pxl = g + 8 * (c >> 1);
            int co = nt * 8 + 2 * t4 + (c & 1);
            stg[(wid * 16 + pxl) * 69 + co] = acc[nt][c] + __ldg(rb + co);
        }
    }
    __syncwarp();

    // --- phase 2: circuit, 2 pixels in flight per pass ---
    int q0 = ring_src(lane), q1 = ring_src(lane + 32);
    int q0l = q0 & 31, q0h = q0 >> 5;
    int q1l = q1 & 31, q1h = q1 >> 5;
    float obr0 = __ldg(ob + lane), obr1 = __ldg(ob + lane + 32);
    float owA[6], owB[6];
#pragma unroll
    for (int i = 0; i < 6; i++) {
        owA[i] = __ldg(ow + lane * 6 + i);
        owB[i] = __ldg(ow + (lane + 32) * 6 + i);
    }

    for (int pp = 0; pp < 8; pp++) {
        float phiA = (lane < 6) ? sphi[pp * 6 + lane] : 0.f;
        float phiB = (lane < 6) ? sphi[(pp + 8) * 6 + lane] : 0.f;
        float svv[2], cvv[2];
        __sincosf(0.5f * phiA, &svv[0], &cvv[0]);
        __sincosf(0.5f * phiB, &svv[1], &cvv[1]);

        float a0r[2] = {1.f, 1.f}, a0i[2] = {0.f, 0.f};
        float a1r[2] = {1.f, 1.f}, a1i[2] = {0.f, 0.f};
#pragma unroll
        for (int i = 0; i < 6; i++) {
            float cb = s_cb0[i], sbv = s_sb0[i];
            int bit = (lane >> (5 - i)) & 1;
#pragma unroll
            for (int j = 0; j < 2; j++) {
                float cv = __shfl_sync(F, cvv[j], i);
                float sv = __shfl_sync(F, svv[j], i);
                float u0r = cv * cb, u0i = -cv * sbv;
                float u1r = sv * cb, u1i = sv * sbv;
                float ur0 = bit ? u1r : u0r, ui0 = bit ? u1i : u0i;
                float ur1 = (i == 0) ? u1r : ur0, ui1 = (i == 0) ? u1i : ui0;
                float nr = a0r[j] * ur0 - a0i[j] * ui0;
                float ni = a0r[j] * ui0 + a0i[j] * ur0;
                a0r[j] = nr; a0i[j] = ni;
                nr = a1r[j] * ur1 - a1i[j] * ui1;
                ni = a1r[j] * ui1 + a1i[j] * ur1;
                a1r[j] = nr; a1i[j] = ni;
            }
        }

        ring2_2(q0l, q0h, q1l, q1h, a0r, a0i, a1r, a1i);
#pragma unroll
        for (int i = 0; i < 6; i++) {
            if (i == 0) gate_b5_2(s_g1[0], a0r, a0i, a1r, a1i);
            else        gate_lo_2(5 - i, lane, s_g1[i], a0r, a0i, a1r, a1i);
        }
        ring2_2(q0l, q0h, q1l, q1h, a0r, a0i, a1r, a1i);
#pragma unroll
        for (int i = 0; i < 6; i++) {
            if (i == 0) gate_b5_2(s_g2[0], a0r, a0i, a1r, a1i);
            else        gate_lo_2(5 - i, lane, s_g2[i], a0r, a0i, a1r, a1i);
        }

#pragma unroll
        for (int j = 0; j < 2; j++) {
            float p0 = a0r[j] * a0r[j] + a0i[j] * a0i[j];
            float p1 = a1r[j] * a1r[j] + a1i[j] * a1i[j];
            float t0 = p0 + p1, dd = p0 - p1;
#pragma unroll
            for (int m = 16; m; m >>= 1) dd += __shfl_xor_sync(F, dd, m);
#pragma unroll
            for (int m = 16; m; m >>= 1) {
                float o = __shfl_xor_sync(F, t0, m);
                t0 = ((lane & m) ? -t0 : t0) + o;
            }
            float e1 = __shfl_sync(F, t0, 16);
            float e2 = __shfl_sync(F, t0, 8);
            float e3 = __shfl_sync(F, t0, 4);
            float e4 = __shfl_sync(F, t0, 2);
            float e5 = __shfl_sync(F, t0, 1);

            float o0 = fmaf(owA[0], dd, obr0);
            float o1 = fmaf(owB[0], dd, obr1);
            o0 = fmaf(owA[1], e1, o0); o1 = fmaf(owB[1], e1, o1);
            o0 = fmaf(owA[2], e2, o0); o1 = fmaf(owB[2], e2, o1);
            o0 = fmaf(owA[3], e3, o0); o1 = fmaf(owB[3], e3, o1);
            o0 = fmaf(owA[4], e4, o0); o1 = fmaf(owB[4], e4, o1);
            o0 = fmaf(owA[5], e5, o0); o1 = fmaf(owB[5], e5, o1);

            int px = wid * 16 + pp + 8 * j;
            stg[px * 69 + lane] += o0;
            stg[px * 69 + lane + 32] += o1;
        }
    }
    __syncthreads();

    // --- fully coalesced final write: 64 co rows x 128 contiguous px ---
    for (int i = tid; i < 8192; i += 256) {
        int co = i >> 7, px = i & 127;
        out[(((b << 6) + co) << 12) + hwbase + px] = stg[px * 69 + co];
    }
}

// ---------------- launch ----------------
extern "C" void kernel_launch(void* const* d_in, const int* in_sizes, int n_in,
                              void* d_out, int out_size) {
    const float* x     = (const float*)d_in[0];
    const float* style = (const float*)d_in[1];
    const float* wd    = (const float*)d_in[2];   // data_proj_w [6,576]
    const float* db    = (const float*)d_in[3];   // data_proj_b [6]
    const float* sw    = (const float*)d_in[4];   // style_to_data_w [6,128]
    const float* sb    = (const float*)d_in[5];   // style_to_data_b [6]
    const float* qcnn  = (const float*)d_in[6];   // [2,6,2,3]
    const float* meas  = (const float*)d_in[7];   // [6,3]
    const float* ow    = (const float*)d_in[8];   // out_proj_w [64,6]
    const float* ob    = (const float*)d_in[9];   // out_proj_b [64]
    const float* wr    = (const float*)d_in[10];  // res_proj_w [64,576]
    const float* rb    = (const float*)d_in[11];  // res_proj_b [64]
    float* out = (float*)d_out;

    cudaFuncSetAttribute(k_fused, cudaFuncAttributeMaxDynamicSharedMemorySize, FUSED_SMEM);
    k_fused<<<256, 256, FUSED_SMEM>>>(x, wr, wd, rb, db, style, sw, sb,
                                      qcnn, meas, ow, ob, out);
}